// round 6
// baseline (speedup 1.0000x reference)
#include <cuda_runtime.h>

// Shapes (fixed):
//   image: (3, 512, 512) f32
//   x:     (16, 1, 512, 512) f32
//   W:     (9, 3, 3, 3) f32   b: (9,) f32
//   out:   (16, 1, 512, 512) f32
//
// K[c,i,j] = b[c] + sum_{m,u,v} W[c,m,u,v] * image[m, i+u-1, j+v-1]  (zero pad)
// y[n,i,j] = sum_{u,v} x[n, i+u-1, j+v-1] * K[u*3+v, i, j]           (zero pad)

#define HH 512
#define WW 512
#define NB 16
#define PLANE (HH * WW)

// Load a 6-wide row window [col0-1 .. col0+4] with zero padding.
__device__ __forceinline__ void load_row6(const float* __restrict__ base,
                                          bool rowok, bool leftok, bool rightok,
                                          float r[6])
{
    if (rowok) {
        float4 v = *(const float4*)base;          // cols col0..col0+3 (16B aligned)
        r[1] = v.x; r[2] = v.y; r[3] = v.z; r[4] = v.w;
        r[0] = leftok  ? base[-1] : 0.0f;
        r[5] = rightok ? base[4]  : 0.0f;
    } else {
        r[0] = r[1] = r[2] = r[3] = r[4] = r[5] = 0.0f;
    }
}

// Full 3x6 stencil window centered on row i.
__device__ __forceinline__ void load_win3(const float* __restrict__ cbase,
                                          bool rok0, bool rok2,
                                          bool lok, bool rtok,
                                          float r[3][6])
{
    load_row6(cbase - WW, rok0, lok, rtok, r[0]);
    load_row6(cbase,      true, lok, rtok, r[1]);
    load_row6(cbase + WW, rok2, lok, rtok, r[2]);
}

// Apply the 4 per-pixel 3x3 kernels to a loaded window.
__device__ __forceinline__ float4 apply_win(const float r[3][6], const float K[36])
{
    float a0 = 0.f, a1 = 0.f, a2 = 0.f, a3 = 0.f;
    #pragma unroll
    for (int u = 0; u < 3; u++) {
        #pragma unroll
        for (int v = 0; v < 3; v++) {
            const int c = u * 3 + v;
            a0 = fmaf(r[u][v + 0], K[c * 4 + 0], a0);
            a1 = fmaf(r[u][v + 1], K[c * 4 + 1], a1);
            a2 = fmaf(r[u][v + 2], K[c * 4 + 2], a2);
            a3 = fmaf(r[u][v + 3], K[c * 4 + 3], a3);
        }
    }
    float4 o; o.x = a0; o.y = a1; o.z = a2; o.w = a3;
    return o;
}

__global__ __launch_bounds__(128)
void fused_dynconv4d(const float* __restrict__ image,
                     const float* __restrict__ x,
                     const float* __restrict__ Wt,
                     const float* __restrict__ bb,
                     float* __restrict__ y)
{
    // W transposed: Wtr[t*12 + c] = W[c*27 + t]; stride 12 keeps rows 16B aligned.
    __shared__ float Wtr[27 * 12];
    __shared__ float bsh[9];

    const int tx  = threadIdx.x;          // 0..31
    const int ty  = threadIdx.y;          // 0..3
    const int tid = ty * 32 + tx;

    for (int idx = tid; idx < 243; idx += 128) {
        int c = idx / 27;
        int t = idx % 27;
        Wtr[t * 12 + c] = Wt[idx];
    }
    if (tid < 9) bsh[tid] = bb[tid];
    __syncthreads();   // only barrier

    const int col0 = (blockIdx.x * 32 + tx) * 4;   // 4 px per thread, 16B aligned
    const int i    = blockIdx.y * 4 + ty;

    const bool rok0 = (i > 0);
    const bool rok2 = (i < HH - 1);
    const bool lok  = (col0 > 0);
    const bool rtok = (col0 < WW - 4);

    const float* xb = x + (size_t)i * WW + col0;
    float*       yb = y + (size_t)i * WW + col0;
    const float* ib = image + (size_t)i * WW + col0;

    // ---- deep prefetch: x slices 0,1 AND image plane 0 all in flight ----
    float X[3][3][6];                       // rotating x-window buffers
    load_win3(xb,         rok0, rok2, lok, rtok, X[0]);
    load_win3(xb + PLANE, rok0, rok2, lok, rtok, X[1]);

    float I[2][3][6];                       // double-buffered image planes
    load_win3(ib, rok0, rok2, lok, rtok, I[0]);

    // ---------------- K stage: per-pixel 3x3 kernels for 4 pixels ----------------
    float K[36];   // K[c*4 + p]
    #pragma unroll
    for (int c = 0; c < 9; c++) {
        float bc = bsh[c];
        K[c * 4 + 0] = bc; K[c * 4 + 1] = bc;
        K[c * 4 + 2] = bc; K[c * 4 + 3] = bc;
    }

    #pragma unroll
    for (int m = 0; m < 3; m++) {
        if (m < 2)   // prefetch next image plane before computing this one
            load_win3(ib + (size_t)(m + 1) * PLANE, rok0, rok2, lok, rtok,
                      I[(m + 1) & 1]);

        const float (*r)[6] = I[m & 1];
        #pragma unroll
        for (int u = 0; u < 3; u++) {
            #pragma unroll
            for (int v = 0; v < 3; v++) {
                const int t = m * 9 + u * 3 + v;
                float4 w0 = *(const float4*)&Wtr[t * 12];
                float4 w1 = *(const float4*)&Wtr[t * 12 + 4];
                float  w8 = Wtr[t * 12 + 8];
                float wv[9] = {w0.x, w0.y, w0.z, w0.w, w1.x, w1.y, w1.z, w1.w, w8};
                #pragma unroll
                for (int c = 0; c < 9; c++) {
                    #pragma unroll
                    for (int p = 0; p < 4; p++)
                        K[c * 4 + p] = fmaf(wv[c], r[u][v + p], K[c * 4 + p]);
                }
            }
        }
    }

    // -------- apply stage: 3-buffer rotation, prefetch distance 2 --------
    #pragma unroll
    for (int n = 0; n < NB; n++) {
        if (n + 2 < NB)
            load_win3(xb + (size_t)(n + 2) * PLANE, rok0, rok2, lok, rtok,
                      X[(n + 2) % 3]);

        *(float4*)(yb + (size_t)n * PLANE) = apply_win(X[n % 3], K);
    }
}

extern "C" void kernel_launch(void* const* d_in, const int* in_sizes, int n_in,
                              void* d_out, int out_size)
{
    const float* image = (const float*)d_in[0];   // 3*512*512
    const float* x     = (const float*)d_in[1];   // 16*512*512
    const float* Wt    = (const float*)d_in[2];   // 243
    const float* bb    = (const float*)d_in[3];   // 9
    float* y = (float*)d_out;                     // 16*512*512

    dim3 block(32, 4);                 // 128 threads, each owns 4 horizontal pixels
    dim3 grid(WW / (32 * 4), HH / 4);  // (4, 128) = 512 blocks
    fused_dynconv4d<<<grid, block>>>(image, x, Wt, bb, y);
}

// round 7
// speedup vs baseline: 1.2211x; 1.2211x over previous
#include <cuda_runtime.h>

// Shapes (fixed):
//   image: (3, 512, 512) f32
//   x:     (16, 1, 512, 512) f32
//   W:     (9, 3, 3, 3) f32   b: (9,) f32
//   out:   (16, 1, 512, 512) f32
//
// Stage A: K[c,i,j] = b[c] + sum_{m,u,v} W[c,m,u,v]*image[m,i+u-1,j+v-1]
// Stage B: y[n,i,j] = sum_{u,v} x[n,i+u-1,j+v-1] * K[u*3+v,i,j]
// K (9 planes, 9.4 MB) is materialized in a __device__ scratch; it stays
// L2-resident between the two launches.

#define HH 512
#define WW 512
#define NB 16
#define PLANE (HH * WW)

__device__ float Kscratch[9 * PLANE];   // 9.4 MB scratch (allowed: static device array)

// ---------------------------------------------------------------------------
// Kernel A: per-pixel 3x3 kernels from the 3->9 channel conv. 2 px/thread.
// ---------------------------------------------------------------------------
__global__ __launch_bounds__(128)
void kernelK(const float* __restrict__ image,
             const float* __restrict__ Wt,
             const float* __restrict__ bb)
{
    // Plain c-major weights, padded to 28 so each channel row is 16B-aligned.
    __shared__ __align__(16) float Wsh[9 * 28];
    __shared__ float bsh[9];

    const int tx = threadIdx.x;          // 0..127
    for (int idx = tx; idx < 243; idx += 128) {
        int c = idx / 27;
        int t = idx % 27;
        Wsh[c * 28 + t] = Wt[idx];
    }
    if (tx < 9) bsh[tx] = bb[tx];
    __syncthreads();

    const int col0 = blockIdx.x * 256 + tx * 2;   // 2 px per thread (8B aligned)
    const int i    = blockIdx.y;                  // row 0..511

    const bool rok0 = (i > 0);
    const bool rok2 = (i < HH - 1);
    const bool lok  = (col0 > 0);
    const bool rtok = (col0 < WW - 2);

    // Load 3x4 window per channel: all 36 values in registers.
    float win[3][3][4];   // [m][row][col], cols col0-1..col0+2
    const float* base = image + (size_t)i * WW + col0;
    #pragma unroll
    for (int m = 0; m < 3; m++) {
        const float* bm = base + (size_t)m * PLANE;
        #pragma unroll
        for (int u = 0; u < 3; u++) {
            const float* p = bm + (u - 1) * WW;
            bool rowok = (u == 1) ? true : (u == 0 ? rok0 : rok2);
            float2 v = make_float2(0.f, 0.f);
            if (rowok) v = *(const float2*)p;
            win[m][u][1] = v.x;
            win[m][u][2] = v.y;
            win[m][u][0] = (rowok && lok)  ? p[-1] : 0.f;
            win[m][u][3] = (rowok && rtok) ? p[2]  : 0.f;
        }
    }

    // K[c] for both pixels: loop c outer, load that channel's 27 weights
    // (7x LDS.128), 54 FMA per c.
    float* kout = Kscratch + (size_t)i * WW + col0;
    #pragma unroll
    for (int c = 0; c < 9; c++) {
        float4 wa = *(const float4*)&Wsh[c * 28 + 0];
        float4 wb = *(const float4*)&Wsh[c * 28 + 4];
        float4 wc = *(const float4*)&Wsh[c * 28 + 8];
        float4 wd = *(const float4*)&Wsh[c * 28 + 12];
        float4 we = *(const float4*)&Wsh[c * 28 + 16];
        float4 wf = *(const float4*)&Wsh[c * 28 + 20];
        float4 wg = *(const float4*)&Wsh[c * 28 + 24];
        float wv[27] = {wa.x, wa.y, wa.z, wa.w, wb.x, wb.y, wb.z, wb.w,
                        wc.x, wc.y, wc.z, wc.w, wd.x, wd.y, wd.z, wd.w,
                        we.x, we.y, we.z, we.w, wf.x, wf.y, wf.z, wf.w,
                        wg.x, wg.y, wg.z};
        float k0 = bsh[c], k1 = bsh[c];
        #pragma unroll
        for (int m = 0; m < 3; m++) {
            #pragma unroll
            for (int u = 0; u < 3; u++) {
                #pragma unroll
                for (int v = 0; v < 3; v++) {
                    float w = wv[m * 9 + u * 3 + v];
                    k0 = fmaf(w, win[m][u][v + 0], k0);
                    k1 = fmaf(w, win[m][u][v + 1], k1);
                }
            }
        }
        *(float2*)(kout + (size_t)c * PLANE) = make_float2(k0, k1);
    }
}

// ---------------------------------------------------------------------------
// Kernel B: apply per-pixel kernels to 8 x-slices per block. 2 px/thread.
// ---------------------------------------------------------------------------
__global__ __launch_bounds__(128)
void kernelApply(const float* __restrict__ x,
                 float* __restrict__ y)
{
    const int tx   = threadIdx.x;                  // 0..127
    const int col0 = blockIdx.x * 256 + tx * 2;    // 2 px per thread
    const int i    = blockIdx.y;                   // row
    const int n0   = blockIdx.z * 8;               // slice group

    const bool rok0 = (i > 0);
    const bool rok2 = (i < HH - 1);
    const bool lok  = (col0 > 0);
    const bool rtok = (col0 < WW - 2);

    // Load this pixel pair's 9 kernel taps (L2-resident).
    float K0[9], K1[9];
    {
        const float* kb = Kscratch + (size_t)i * WW + col0;
        #pragma unroll
        for (int c = 0; c < 9; c++) {
            float2 kv = *(const float2*)(kb + (size_t)c * PLANE);
            K0[c] = kv.x;
            K1[c] = kv.y;
        }
    }

    const float* xb = x + (size_t)n0 * PLANE + (size_t)i * WW + col0;
    float*       yb = y + (size_t)n0 * PLANE + (size_t)i * WW + col0;

    #pragma unroll
    for (int n = 0; n < 8; n++) {
        // 3x4 window, zero padded
        float r[3][4];
        #pragma unroll
        for (int u = 0; u < 3; u++) {
            const float* p = xb + (u - 1) * WW;
            bool rowok = (u == 1) ? true : (u == 0 ? rok0 : rok2);
            float2 v = make_float2(0.f, 0.f);
            if (rowok) v = *(const float2*)p;
            r[u][1] = v.x;
            r[u][2] = v.y;
            r[u][0] = (rowok && lok)  ? p[-1] : 0.f;
            r[u][3] = (rowok && rtok) ? p[2]  : 0.f;
        }

        float a0 = 0.f, a1 = 0.f;
        #pragma unroll
        for (int u = 0; u < 3; u++) {
            #pragma unroll
            for (int v = 0; v < 3; v++) {
                const int c = u * 3 + v;
                a0 = fmaf(r[u][v + 0], K0[c], a0);
                a1 = fmaf(r[u][v + 1], K1[c], a1);
            }
        }
        *(float2*)yb = make_float2(a0, a1);

        xb += PLANE;
        yb += PLANE;
    }
}

extern "C" void kernel_launch(void* const* d_in, const int* in_sizes, int n_in,
                              void* d_out, int out_size)
{
    const float* image = (const float*)d_in[0];   // 3*512*512
    const float* x     = (const float*)d_in[1];   // 16*512*512
    const float* Wt    = (const float*)d_in[2];   // 243
    const float* bb    = (const float*)d_in[3];   // 9
    float* y = (float*)d_out;                     // 16*512*512

    dim3 blockA(128);
    dim3 gridA(WW / 256, HH);        // (2, 512) = 1024 blocks
    kernelK<<<gridA, blockA>>>(image, Wt, bb);

    dim3 blockB(128);
    dim3 gridB(WW / 256, HH, 2);     // (2, 512, 2) = 2048 blocks, 8 slices each
    kernelApply<<<gridB, blockB>>>(x, y);
}

// round 8
// speedup vs baseline: 1.2878x; 1.0546x over previous
#include <cuda_runtime.h>

// Shapes (fixed):
//   image: (3, 512, 512) f32
//   x:     (16, 1, 512, 512) f32
//   W:     (9, 3, 3, 3) f32   b: (9,) f32
//   out:   (16, 1, 512, 512) f32
//
// Stage A: K[c,i,j] = b[c] + sum_{m,u,v} W[c,m,u,v]*image[m,i+u-1,j+v-1]
// Stage B: y[n,i,j] = sum_{u,v} x[n,i+u-1,j+v-1] * K[u*3+v,i,j]
// K (9 planes, 9.4 MB) is materialized in __device__ scratch (L2-resident).

#define HH 512
#define WW 512
#define NB 16
#define PLANE (HH * WW)

__device__ float Kscratch[9 * PLANE];   // 9.4 MB static device scratch

// ---------------------------------------------------------------------------
// Kernel A: per-pixel 3x3 kernels from the 3->9 channel conv. 2 px/thread.
// ---------------------------------------------------------------------------
__global__ __launch_bounds__(128)
void kernelK(const float* __restrict__ image,
             const float* __restrict__ Wt,
             const float* __restrict__ bb)
{
    // Plain c-major weights, padded to 28 so each channel row is 16B-aligned.
    __shared__ __align__(16) float Wsh[9 * 28];
    __shared__ float bsh[9];

    const int tx = threadIdx.x;          // 0..127
    for (int idx = tx; idx < 243; idx += 128) {
        int c = idx / 27;
        int t = idx % 27;
        Wsh[c * 28 + t] = Wt[idx];
    }
    if (tx < 9) bsh[tx] = bb[tx];
    __syncthreads();

    const int col0 = blockIdx.x * 256 + tx * 2;   // 2 px per thread (8B aligned)
    const int i    = blockIdx.y;                  // row 0..511

    const bool rok0 = (i > 0);
    const bool rok2 = (i < HH - 1);
    const bool lok  = (col0 > 0);
    const bool rtok = (col0 < WW - 2);

    // Load 3x4 window per channel: all 36 values in registers.
    float win[3][3][4];   // [m][row][col], cols col0-1..col0+2
    const float* base = image + (size_t)i * WW + col0;
    #pragma unroll
    for (int m = 0; m < 3; m++) {
        const float* bm = base + (size_t)m * PLANE;
        #pragma unroll
        for (int u = 0; u < 3; u++) {
            const float* p = bm + (u - 1) * WW;
            bool rowok = (u == 1) ? true : (u == 0 ? rok0 : rok2);
            float2 v = make_float2(0.f, 0.f);
            if (rowok) v = *(const float2*)p;
            win[m][u][1] = v.x;
            win[m][u][2] = v.y;
            win[m][u][0] = (rowok && lok)  ? p[-1] : 0.f;
            win[m][u][3] = (rowok && rtok) ? p[2]  : 0.f;
        }
    }

    float* kout = Kscratch + (size_t)i * WW + col0;
    #pragma unroll
    for (int c = 0; c < 9; c++) {
        float4 wa = *(const float4*)&Wsh[c * 28 + 0];
        float4 wb = *(const float4*)&Wsh[c * 28 + 4];
        float4 wc = *(const float4*)&Wsh[c * 28 + 8];
        float4 wd = *(const float4*)&Wsh[c * 28 + 12];
        float4 we = *(const float4*)&Wsh[c * 28 + 16];
        float4 wf = *(const float4*)&Wsh[c * 28 + 20];
        float4 wg = *(const float4*)&Wsh[c * 28 + 24];
        float wv[27] = {wa.x, wa.y, wa.z, wa.w, wb.x, wb.y, wb.z, wb.w,
                        wc.x, wc.y, wc.z, wc.w, wd.x, wd.y, wd.z, wd.w,
                        we.x, we.y, we.z, we.w, wf.x, wf.y, wf.z, wf.w,
                        wg.x, wg.y, wg.z};
        float k0 = bsh[c], k1 = bsh[c];
        #pragma unroll
        for (int m = 0; m < 3; m++) {
            #pragma unroll
            for (int u = 0; u < 3; u++) {
                #pragma unroll
                for (int v = 0; v < 3; v++) {
                    float w = wv[m * 9 + u * 3 + v];
                    k0 = fmaf(w, win[m][u][v + 0], k0);
                    k1 = fmaf(w, win[m][u][v + 1], k1);
                }
            }
        }
        *(float2*)(kout + (size_t)c * PLANE) = make_float2(k0, k1);
    }
}

// ---------------------------------------------------------------------------
// Kernel B: apply per-pixel kernels, 8 x-slices per block, 2 px/thread,
// triple-buffered windows with prefetch distance 2 (explicit SW pipeline).
// ---------------------------------------------------------------------------

// 4-wide window (cols col0-1..col0+2), 3 rows, zero padded.
__device__ __forceinline__ void load_win4(const float* __restrict__ cb,
                                          bool rok0, bool rok2,
                                          bool lok, bool rtok,
                                          float r[3][4])
{
    #pragma unroll
    for (int u = 0; u < 3; u++) {
        const float* p = cb + (u - 1) * WW;
        bool rowok = (u == 1) ? true : (u == 0 ? rok0 : rok2);
        float2 v = make_float2(0.f, 0.f);
        if (rowok) v = *(const float2*)p;
        r[u][1] = v.x;
        r[u][2] = v.y;
        r[u][0] = (rowok && lok)  ? p[-1] : 0.f;
        r[u][3] = (rowok && rtok) ? p[2]  : 0.f;
    }
}

__global__ __launch_bounds__(128)
void kernelApply(const float* __restrict__ x,
                 float* __restrict__ y)
{
    const int tx   = threadIdx.x;                  // 0..127
    const int col0 = blockIdx.x * 256 + tx * 2;    // 2 px per thread
    const int i    = blockIdx.y;                   // row
    const int n0   = blockIdx.z * 8;               // slice group

    const bool rok0 = (i > 0);
    const bool rok2 = (i < HH - 1);
    const bool lok  = (col0 > 0);
    const bool rtok = (col0 < WW - 2);

    const float* xb = x + (size_t)n0 * PLANE + (size_t)i * WW + col0;
    float*       yb = y + (size_t)n0 * PLANE + (size_t)i * WW + col0;

    // Start the x pipeline FIRST so slices 0,1 fly while K loads resolve.
    float Xw[3][3][4];
    load_win4(xb,         rok0, rok2, lok, rtok, Xw[0]);
    load_win4(xb + PLANE, rok0, rok2, lok, rtok, Xw[1]);

    // Pixel pair's 9 kernel taps (L2-resident from kernel A).
    float K0[9], K1[9];
    {
        const float* kb = Kscratch + (size_t)i * WW + col0;
        #pragma unroll
        for (int c = 0; c < 9; c++) {
            float2 kv = *(const float2*)(kb + (size_t)c * PLANE);
            K0[c] = kv.x;
            K1[c] = kv.y;
        }
    }

    #pragma unroll
    for (int n = 0; n < 8; n++) {
        if (n + 2 < 8)   // prefetch distance 2
            load_win4(xb + (size_t)(n + 2) * PLANE, rok0, rok2, lok, rtok,
                      Xw[(n + 2) % 3]);

        const float (*r)[4] = Xw[n % 3];
        float a0 = 0.f, a1 = 0.f;
        #pragma unroll
        for (int u = 0; u < 3; u++) {
            #pragma unroll
            for (int v = 0; v < 3; v++) {
                const int c = u * 3 + v;
                a0 = fmaf(r[u][v + 0], K0[c], a0);
                a1 = fmaf(r[u][v + 1], K1[c], a1);
            }
        }
        *(float2*)(yb + (size_t)n * PLANE) = make_float2(a0, a1);
    }
}

extern "C" void kernel_launch(void* const* d_in, const int* in_sizes, int n_in,
                              void* d_out, int out_size)
{
    const float* image = (const float*)d_in[0];   // 3*512*512
    const float* x     = (const float*)d_in[1];   // 16*512*512
    const float* Wt    = (const float*)d_in[2];   // 243
    const float* bb    = (const float*)d_in[3];   // 9
    float* y = (float*)d_out;                     // 16*512*512

    dim3 blockA(128);
    dim3 gridA(WW / 256, HH);        // (2, 512) = 1024 blocks
    kernelK<<<gridA, blockA>>>(image, Wt, bb);

    dim3 blockB(128);
    dim3 gridB(WW / 256, HH, 2);     // (2, 512, 2) = 2048 blocks, 8 slices each
    kernelApply<<<gridB, blockB>>>(x, y);
}